// round 4
// baseline (speedup 1.0000x reference)
#include <cuda_runtime.h>
#include <math.h>

#define N_COLS 4096
#define TPB    256
#define EPS    1e-14f

// published once by block 0: s2 = 2 / (||v|| + eps)^2
__device__ float g_s2;
__device__ int   g_flag;   // 0 -> not ready; 1 -> ready (persists across replays;
                           // value is identical every replay, so stale reads are benign)

__global__ void __launch_bounds__(TPB, 5)
householder_kernel(const float* __restrict__ x,
                   const float* __restrict__ v,
                   const float* __restrict__ bias,
                   float* __restrict__ out) {
    const int tid = threadIdx.x;
    const int w = tid >> 5, l = tid & 31;
    const int row = blockIdx.x;

    const float4* __restrict__ xr = (const float4*)(x + (size_t)row * N_COLS);
    const float4* __restrict__ vr = (const float4*)v;
    const float4* __restrict__ br = (const float4*)bias;
    float4* __restrict__       orow = (float4*)(out + (size_t)row * N_COLS);

    __shared__ float red[TPB / 32];
    __shared__ float s2_sh;

    // ---- block 0 additionally computes and publishes s2 (it never waits) ----
    if (row == 0) {
        float vn = 0.0f;
        #pragma unroll
        for (int j = 0; j < 4; j++) {
            float4 t = vr[tid + j * TPB];
            vn = fmaf(t.x, t.x, vn);
            vn = fmaf(t.y, t.y, vn);
            vn = fmaf(t.z, t.z, vn);
            vn = fmaf(t.w, t.w, vn);
        }
        #pragma unroll
        for (int o = 16; o > 0; o >>= 1)
            vn += __shfl_xor_sync(0xffffffffu, vn, o);
        if (l == 0) red[w] = vn;
        __syncthreads();
        if (tid == 0) {
            float t = 0.0f;
            #pragma unroll
            for (int i = 0; i < TPB / 32; i++) t += red[i];
            float s = 1.0f / (sqrtf(t) + EPS);
            g_s2 = 2.0f * s * s;
            __threadfence();
            atomicExch(&g_flag, 1);        // release
        }
        __syncthreads();                   // red[] reused below
    }

    // ---- load row, dot with v (v loads are L1/L2 broadcast-hot) ----
    float4 xv[4];
    float dot = 0.0f;
    #pragma unroll
    for (int j = 0; j < 4; j++) {
        const int idx = tid + j * TPB;     // coalesced 128B per warp
        xv[j] = xr[idx];
        float4 t = vr[idx];
        dot = fmaf(xv[j].x, t.x, dot);
        dot = fmaf(xv[j].y, t.y, dot);
        dot = fmaf(xv[j].z, t.z, dot);
        dot = fmaf(xv[j].w, t.w, dot);
    }
    #pragma unroll
    for (int o = 16; o > 0; o >>= 1)
        dot += __shfl_xor_sync(0xffffffffu, dot, o);
    if (l == 0) red[w] = dot;

    // one thread fetches s2 while the barrier forms (block 0 published long ago
    // for every block except itself, where it's already set)
    if (tid == 0) {
        while (atomicAdd(&g_flag, 0) == 0) { __nanosleep(64); }  // acquire-poll
        __threadfence();
        s2_sh = *(volatile float*)&g_s2;
    }
    __syncthreads();

    float t = 0.0f;
    #pragma unroll
    for (int i = 0; i < TPB / 32; i++) t += red[i];   // broadcast LDS
    const float coef = t * s2_sh;

    // ---- epilogue: reload v (L1-hot) + bias, fuse, store ----
    #pragma unroll
    for (int j = 0; j < 4; j++) {
        const int idx = tid + j * TPB;
        float4 vvj = vr[idx];
        float4 bb  = br[idx];
        float4 o4;
        o4.x = fmaf(-coef, vvj.x, xv[j].x) + bb.x;
        o4.y = fmaf(-coef, vvj.y, xv[j].y) + bb.y;
        o4.z = fmaf(-coef, vvj.z, xv[j].z) + bb.z;
        o4.w = fmaf(-coef, vvj.w, xv[j].w) + bb.w;
        orow[idx] = o4;
    }
}

extern "C" void kernel_launch(void* const* d_in, const int* in_sizes, int n_in,
                              void* d_out, int out_size) {
    const float* x    = (const float*)d_in[0];   // [16384, 4096]
    const float* v    = (const float*)d_in[1];   // [4096, 1]
    const float* bias = (const float*)d_in[2];   // [4096]
    float* out = (float*)d_out;

    const int n_rows = in_sizes[0] / N_COLS;     // 16384

    householder_kernel<<<n_rows, TPB>>>(x, v, bias, out);
}

// round 5
// speedup vs baseline: 1.0550x; 1.0550x over previous
#include <cuda_runtime.h>
#include <math.h>

#define N_COLS 4096
#define TPB    256
#define EPS    1e-14f

// One block per row, fully fused, ONE barrier per block:
// out[i] = x[i] - (2*(x.v)/(||v||+eps)^2) * v[i] + bias[i]
__global__ void __launch_bounds__(TPB, 5)
householder_kernel(const float* __restrict__ x,
                   const float* __restrict__ v,
                   const float* __restrict__ bias,
                   float* __restrict__ out) {
    const int tid = threadIdx.x;
    const int w = tid >> 5, l = tid & 31;
    const int row = blockIdx.x;

    const float4* __restrict__ xr = (const float4*)(x + (size_t)row * N_COLS);
    const float4* __restrict__ vr = (const float4*)v;
    const float4* __restrict__ br = (const float4*)bias;
    float4* __restrict__       orow = (float4*)(out + (size_t)row * N_COLS);

    __shared__ float red_d[TPB / 32];
    __shared__ float red_n[TPB / 32];

    // ---- single pass: load row + v, accumulate dot and ||v||^2 ----
    float4 xv[4];
    float dot = 0.0f, vn = 0.0f;
    #pragma unroll
    for (int j = 0; j < 4; j++) {
        const int idx = tid + j * TPB;     // coalesced 128B per warp
        xv[j] = xr[idx];
        float4 t = vr[idx];                // L1/L2 broadcast-hot (16KB)
        dot = fmaf(xv[j].x, t.x, dot);
        dot = fmaf(xv[j].y, t.y, dot);
        dot = fmaf(xv[j].z, t.z, dot);
        dot = fmaf(xv[j].w, t.w, dot);
        vn  = fmaf(t.x, t.x, vn);
        vn  = fmaf(t.y, t.y, vn);
        vn  = fmaf(t.z, t.z, vn);
        vn  = fmaf(t.w, t.w, vn);
    }

    #pragma unroll
    for (int o = 16; o > 0; o >>= 1) {
        dot += __shfl_xor_sync(0xffffffffu, dot, o);
        vn  += __shfl_xor_sync(0xffffffffu, vn,  o);
    }
    if (l == 0) { red_d[w] = dot; red_n[w] = vn; }
    __syncthreads();                        // the ONLY barrier

    // every thread finishes the reduction itself (broadcast LDS = conflict-free)
    float td = 0.0f, tn = 0.0f;
    #pragma unroll
    for (int i = 0; i < TPB / 32; i++) { td += red_d[i]; tn += red_n[i]; }
    const float s = 1.0f / (sqrtf(tn) + EPS);
    const float coef = 2.0f * td * s * s;

    // ---- epilogue: reload v (L1-hot) + bias, fuse, store ----
    #pragma unroll
    for (int j = 0; j < 4; j++) {
        const int idx = tid + j * TPB;
        float4 vvj = vr[idx];
        float4 bb  = br[idx];
        float4 o4;
        o4.x = fmaf(-coef, vvj.x, xv[j].x) + bb.x;
        o4.y = fmaf(-coef, vvj.y, xv[j].y) + bb.y;
        o4.z = fmaf(-coef, vvj.z, xv[j].z) + bb.z;
        o4.w = fmaf(-coef, vvj.w, xv[j].w) + bb.w;
        orow[idx] = o4;
    }
}

extern "C" void kernel_launch(void* const* d_in, const int* in_sizes, int n_in,
                              void* d_out, int out_size) {
    const float* x    = (const float*)d_in[0];   // [16384, 4096]
    const float* v    = (const float*)d_in[1];   // [4096, 1]
    const float* bias = (const float*)d_in[2];   // [4096]
    float* out = (float*)d_out;

    const int n_rows = in_sizes[0] / N_COLS;     // 16384

    householder_kernel<<<n_rows, TPB>>>(x, v, bias, out);
}